// round 16
// baseline (speedup 1.0000x reference)
#include <cuda_runtime.h>
#include <cuda_bf16.h>
#include <math.h>
#include <stdint.h>

// Shapes
#define M_ROWS 4096   // B*T
#define C_DIM  1024
#define FF_DIM 4096
#define A_DIM  64
#define T_LEN  1024
#define NHEAD  16
#define HDIM   64

// ---------------- scratch (device globals; no allocs allowed) ----------------
__device__ float g_h     [M_ROWS * C_DIM];
__device__ float g_q     [M_ROWS * C_DIM];
__device__ float g_k     [M_ROWS * C_DIM];
__device__ float g_v     [M_ROWS * C_DIM];
__device__ float g_y     [M_ROWS * C_DIM];
__device__ float g_hidden[M_ROWS * C_DIM];
__device__ float g_mlp   [M_ROWS * C_DIM];
__device__ float g_n3    [M_ROWS * C_DIM];
__device__ float g_ad1   [M_ROWS * A_DIM];
__device__ float g_wqt   [C_DIM * C_DIM];          // fp32 transposed weights [N][K]
__device__ float g_wkt   [C_DIM * C_DIM];
__device__ float g_wvt   [C_DIM * C_DIM];
__device__ float g_wot   [C_DIM * C_DIM];
__device__ __nv_bfloat16 g_mb [M_ROWS * C_DIM];    // ln2(hidden) in bf16
__device__ __nv_bfloat16 g_ffb[M_ROWS * FF_DIM];   // gelu(m@w1+b1) in bf16
__device__ __nv_bfloat16 g_w1b[FF_DIM * C_DIM];    // w1^T bf16 [N][K]
__device__ __nv_bfloat16 g_w2b[C_DIM * FF_DIM];    // w2^T bf16 [N][K]

// ======================= helpers ==============================================
__device__ __forceinline__ void cp16(uint32_t dst, const void* src) {
    asm volatile("cp.async.cg.shared.global [%0], [%1], 16;"
                 :: "r"(dst), "l"(src) : "memory");
}
__device__ __forceinline__ uint32_t s2u(const void* p) {
    uint32_t a;
    asm("{ .reg .u64 t; cvta.to.shared.u64 t, %1; cvt.u32.u64 %0, t; }"
        : "=r"(a) : "l"(p));
    return a;
}
// Raw fp32 bits fed to tf32 mma: HW uses top 19 bits (RZ-equivalent).
__device__ __forceinline__ uint32_t f2tf32(float x) { return __float_as_uint(x); }

__device__ __forceinline__ void ldsm_x4(uint32_t* r, uint32_t addr) {
    asm volatile("ldmatrix.sync.aligned.m8n8.x4.shared.b16 {%0,%1,%2,%3}, [%4];"
                 : "=r"(r[0]), "=r"(r[1]), "=r"(r[2]), "=r"(r[3]) : "r"(addr));
}

__device__ __forceinline__ void mma_tf32(float* c, const uint32_t* a, const uint32_t* b) {
    asm volatile(
        "mma.sync.aligned.m16n8k8.row.col.f32.tf32.tf32.f32 "
        "{%0,%1,%2,%3}, {%4,%5,%6,%7}, {%8,%9}, {%0,%1,%2,%3};"
        : "+f"(c[0]), "+f"(c[1]), "+f"(c[2]), "+f"(c[3])
        : "r"(a[0]), "r"(a[1]), "r"(a[2]), "r"(a[3]), "r"(b[0]), "r"(b[1]));
}
__device__ __forceinline__ void mma_bf16(float* c, const uint32_t* a, const uint32_t* b) {
    asm volatile(
        "mma.sync.aligned.m16n8k16.row.col.f32.bf16.bf16.f32 "
        "{%0,%1,%2,%3}, {%4,%5,%6,%7}, {%8,%9}, {%0,%1,%2,%3};"
        : "+f"(c[0]), "+f"(c[1]), "+f"(c[2]), "+f"(c[3])
        : "r"(a[0]), "r"(a[1]), "r"(a[2]), "r"(a[3]), "r"(b[0]), "r"(b[1]));
}
__device__ __forceinline__ float gelu_exact(float x) {
    return 0.5f * x * (1.0f + erff(x * 0.7071067811865476f));
}

// ============ tf32 GEMM, transposed-B ([N][K]) all-ldmatrix core ==============
// A fp32 [M][K], WT fp32 [N][K]. Tile MI*32 x 128. K staged by 32, 2 stages.
#define T_LD 36
#define T_B_STAGE_F (128 * T_LD)    // 4608

template <int MI>
__host__ __device__ constexpr int tn_stage_f() { return MI * 32 * T_LD + T_B_STAGE_F; }
template <int MI>
__host__ __device__ constexpr int tn_smem() { return 2 * tn_stage_f<MI>() * 4; }

// RMODE: 0 none, 1 out += res1, 2 out += 2*res1 + res2
template <int ACT, int RMODE, int MI>
__device__ __forceinline__ void tn_core(
    const float* __restrict__ A, const float* __restrict__ WT,
    const float* __restrict__ bias,
    const float* __restrict__ res1, const float* __restrict__ res2,
    float* __restrict__ C, int N, int K, int m0, int n0, float* smem)
{
    const int A_STAGE_F = MI * 32 * T_LD;
    const int STAGE_F = A_STAGE_F + T_B_STAGE_F;

    const int tid  = threadIdx.x;
    const int wid  = tid >> 5;
    const int lane = tid & 31;
    const int g    = lane >> 2;
    const int tig  = lane & 3;
    const int wm   = wid >> 2;       // 0..1
    const int wn   = wid & 3;        // 0..3

    const int a_lrow = lane & 15;
    const int a_koff = (lane >> 4) * 4;
    const int b_row16 = (lane & 7) + (lane >> 4) * 8;   // 2 n-tiles per x4
    const int b_koff  = ((lane >> 3) & 1) * 4;

    const uint32_t sb = s2u(smem);

    auto load_stage = [&](int s, int b) {
        const uint32_t abase = sb + (uint32_t)(b * STAGE_F) * 4;
        const uint32_t bbase = abase + A_STAGE_F * 4;
        const float* Ag = A + (size_t)m0 * K + s * 32;
        const float* Wg = WT + (size_t)n0 * K + s * 32;
#pragma unroll
        for (int i = 0; i < MI; i++) {
            int c = tid + i * 256;
            int row = c >> 3, k4 = c & 7;
            cp16(abase + row * (T_LD * 4) + k4 * 16,
                 Ag + (size_t)row * K + k4 * 4);
        }
#pragma unroll
        for (int i = 0; i < 4; i++) {
            int c = tid + i * 256;
            int row = c >> 3, k4 = c & 7;
            cp16(bbase + row * (T_LD * 4) + k4 * 16,
                 Wg + (size_t)row * K + k4 * 4);
        }
        asm volatile("cp.async.commit_group;" ::: "memory");
    };

    float acc[MI][4][4];
#pragma unroll
    for (int mi = 0; mi < MI; mi++)
#pragma unroll
        for (int ni = 0; ni < 4; ni++)
#pragma unroll
            for (int t = 0; t < 4; t++) acc[mi][ni][t] = 0.f;

    const int NS = K / 32;
    load_stage(0, 0);

    for (int s = 0; s < NS; s++) {
        const int buf = s & 1;
        if (s + 1 < NS) {
            load_stage(s + 1, buf ^ 1);
            asm volatile("cp.async.wait_group 1;" ::: "memory");
        } else {
            asm volatile("cp.async.wait_group 0;" ::: "memory");
        }
        __syncthreads();

        const uint32_t As_u = sb + (uint32_t)(buf * STAGE_F) * 4;
        const uint32_t Bs_u = As_u + (uint32_t)A_STAGE_F * 4;

#pragma unroll
        for (int ks = 0; ks < 4; ks++) {
            uint32_t afr[MI][4];
#pragma unroll
            for (int mi = 0; mi < MI; mi++) {
                ldsm_x4(afr[mi], As_u +
                    (uint32_t)((wm * (MI * 16) + mi * 16 + a_lrow) * T_LD + ks * 8 + a_koff) * 4);
            }
            uint32_t bfr[4][2];
#pragma unroll
            for (int ni = 0; ni < 4; ni += 2) {
                uint32_t t4[4];
                ldsm_x4(t4, Bs_u +
                    (uint32_t)((wn * 32 + ni * 8 + b_row16) * T_LD + ks * 8 + b_koff) * 4);
                bfr[ni][0] = t4[0];     bfr[ni][1] = t4[1];
                bfr[ni + 1][0] = t4[2]; bfr[ni + 1][1] = t4[3];
            }
#pragma unroll
            for (int mi = 0; mi < MI; mi++)
#pragma unroll
                for (int ni = 0; ni < 4; ni++)
                    mma_tf32(acc[mi][ni], afr[mi], bfr[ni]);
        }
        __syncthreads();
    }

#pragma unroll
    for (int mi = 0; mi < MI; mi++) {
        const int r0 = m0 + wm * (MI * 16) + mi * 16 + g;
#pragma unroll
        for (int ni = 0; ni < 4; ni++) {
            const int col = n0 + wn * 32 + ni * 8 + tig * 2;
            const float bx = bias[col], by = bias[col + 1];
#pragma unroll
            for (int hh = 0; hh < 2; hh++) {
                const int row = r0 + hh * 8;
                float cx = acc[mi][ni][hh * 2 + 0] + bx;
                float cy = acc[mi][ni][hh * 2 + 1] + by;
                if (ACT == 1) { cx = gelu_exact(cx); cy = gelu_exact(cy); }
                if (RMODE == 1) {
                    cx += res1[(size_t)row * N + col];
                    cy += res1[(size_t)row * N + col + 1];
                } else if (RMODE == 2) {
                    const float2 h2 = *(const float2*)(res1 + (size_t)row * N + col);
                    const float2 m2 = *(const float2*)(res2 + (size_t)row * N + col);
                    cx += 2.f * h2.x + m2.x;
                    cy += 2.f * h2.y + m2.y;
                }
                *(float2*)(C + (size_t)row * N + col) = make_float2(cx, cy);
            }
        }
    }
}

template <int ACT, int RMODE, int MI>
__global__ __launch_bounds__(256) void tn_gemm(
    const float* __restrict__ A, const float* __restrict__ WT,
    const float* __restrict__ bias,
    const float* __restrict__ res1, const float* __restrict__ res2,
    float* __restrict__ C, int N, int K)
{
    extern __shared__ float smem[];
    tn_core<ACT, RMODE, MI>(A, WT, bias, res1, res2, C, N, K,
                            blockIdx.y * (MI * 32), blockIdx.x * 128, smem);
}

// fused QKV (transposed weights)
__global__ __launch_bounds__(256) void qkv_gemm(
    const float* __restrict__ A,
    const float* __restrict__ wqt, const float* __restrict__ wkt, const float* __restrict__ wvt,
    const float* __restrict__ bq, const float* __restrict__ bk, const float* __restrict__ bv,
    float* __restrict__ q, float* __restrict__ k, float* __restrict__ v)
{
    extern __shared__ float smem[];
    const int mat = blockIdx.x >> 3;
    const int n0  = (blockIdx.x & 7) * 128;
    const float* W = (mat == 0) ? wqt : (mat == 1) ? wkt : wvt;
    const float* B = (mat == 0) ? bq  : (mat == 1) ? bk  : bv;
    float* C       = (mat == 0) ? q   : (mat == 1) ? k   : v;
    tn_core<0, 0, 4>(A, W, B, nullptr, nullptr, C, C_DIM, C_DIM,
                     blockIdx.y * 128, n0, smem);
}

// ============ legacy tf32 GEMM (B row-major) — adapter-up only ================
#define A_LD 36
#define B_LD 132
#define B_STAGE_F (32 * B_LD)

template <int MI>
__host__ __device__ constexpr int gemm_smem() { return 2 * (MI * 32 * A_LD + B_STAGE_F) * 4; }

template <int ACT, int RMODE, int MI>
__global__ __launch_bounds__(256) void tc_gemm(
    const float* __restrict__ A, const float* __restrict__ W,
    const float* __restrict__ bias,
    const float* __restrict__ res1, const float* __restrict__ res2,
    float* __restrict__ C, int N, int K)
{
    extern __shared__ float smem[];
    const int A_STAGE_F = MI * 32 * A_LD;
    const int STAGE_F = A_STAGE_F + B_STAGE_F;
    const int m0 = blockIdx.y * (MI * 32);
    const int n0 = blockIdx.x * 128;

    const int tid  = threadIdx.x;
    const int wid  = tid >> 5;
    const int lane = tid & 31;
    const int g    = lane >> 2;
    const int tig  = lane & 3;
    const int wm   = wid >> 2;
    const int wn   = wid & 3;
    const int a_lrow = lane & 15;
    const int a_koff = (lane >> 4) * 4;
    const uint32_t sb = s2u(smem);

    auto load_stage = [&](int s, int b) {
        const uint32_t abase = sb + (uint32_t)(b * STAGE_F) * 4;
        const uint32_t bbase = abase + A_STAGE_F * 4;
        const float* Ag = A + (size_t)m0 * K + s * 32;
        const float* Wg = W + (size_t)(s * 32) * N + n0;
#pragma unroll
        for (int i = 0; i < MI; i++) {
            int c = tid + i * 256;
            int row = c >> 3, k4 = c & 7;
            cp16(abase + row * (A_LD * 4) + k4 * 16, Ag + (size_t)row * K + k4 * 4);
        }
#pragma unroll
        for (int i = 0; i < 4; i++) {
            int c = tid + i * 256;
            int kr = c >> 5, n4 = c & 31;
            cp16(bbase + kr * (B_LD * 4) + n4 * 16, Wg + (size_t)kr * N + n4 * 4);
        }
        asm volatile("cp.async.commit_group;" ::: "memory");
    };

    float acc[MI][4][4];
#pragma unroll
    for (int mi = 0; mi < MI; mi++)
#pragma unroll
        for (int ni = 0; ni < 4; ni++)
#pragma unroll
            for (int t = 0; t < 4; t++) acc[mi][ni][t] = 0.f;

    const int NS = K / 32;
    load_stage(0, 0);

    for (int s = 0; s < NS; s++) {
        const int buf = s & 1;
        if (s + 1 < NS) {
            load_stage(s + 1, buf ^ 1);
            asm volatile("cp.async.wait_group 1;" ::: "memory");
        } else {
            asm volatile("cp.async.wait_group 0;" ::: "memory");
        }
        __syncthreads();

        const uint32_t As_u = sb + (uint32_t)(buf * STAGE_F) * 4;
        const float* Bs = smem + buf * STAGE_F + A_STAGE_F;

#pragma unroll
        for (int ks = 0; ks < 4; ks++) {
            uint32_t afr[MI][4];
#pragma unroll
            for (int mi = 0; mi < MI; mi++) {
                ldsm_x4(afr[mi], As_u +
                    (uint32_t)((wm * (MI * 16) + mi * 16 + a_lrow) * A_LD + ks * 8 + a_koff) * 4);
            }
            uint32_t bfr[4][2];
#pragma unroll
            for (int ni = 0; ni < 4; ni++) {
                const float* p = Bs + (ks * 8 + tig) * B_LD + wn * 32 + ni * 8 + g;
                bfr[ni][0] = f2tf32(p[0]);
                bfr[ni][1] = f2tf32(p[4 * B_LD]);
            }
#pragma unroll
            for (int mi = 0; mi < MI; mi++)
#pragma unroll
                for (int ni = 0; ni < 4; ni++)
                    mma_tf32(acc[mi][ni], afr[mi], bfr[ni]);
        }
        __syncthreads();
    }

#pragma unroll
    for (int mi = 0; mi < MI; mi++) {
        const int r0 = m0 + wm * (MI * 16) + mi * 16 + g;
#pragma unroll
        for (int ni = 0; ni < 4; ni++) {
            const int col = n0 + wn * 32 + ni * 8 + tig * 2;
            const float bx = bias[col], by = bias[col + 1];
#pragma unroll
            for (int hh = 0; hh < 2; hh++) {
                const int row = r0 + hh * 8;
                float cx = acc[mi][ni][hh * 2 + 0] + bx;
                float cy = acc[mi][ni][hh * 2 + 1] + by;
                if (ACT == 1) { cx = gelu_exact(cx); cy = gelu_exact(cy); }
                if (RMODE == 1) {
                    cx += res1[(size_t)row * N + col];
                    cy += res1[(size_t)row * N + col + 1];
                } else if (RMODE == 2) {
                    const float2 h2 = *(const float2*)(res1 + (size_t)row * N + col);
                    const float2 m2 = *(const float2*)(res2 + (size_t)row * N + col);
                    cx += 2.f * h2.x + m2.x;
                    cy += 2.f * h2.y + m2.y;
                }
                *(float2*)(C + (size_t)row * N + col) = make_float2(cx, cy);
            }
        }
    }
}

// ==================== bf16 m16n8k16 GEMM (MLP path) ==========================
#define BH_LD 40
#define BH_A_BYTES (128 * BH_LD * 2)
#define BH_STAGE_BYTES (2 * BH_A_BYTES)
#define BH_SMEM (2 * BH_STAGE_BYTES)

template <int ACT, bool OUTBF>
__global__ __launch_bounds__(256) void bf16_gemm(
    const __nv_bfloat16* __restrict__ A, const __nv_bfloat16* __restrict__ WT,
    const float* __restrict__ bias, void* __restrict__ Cout, int N, int K)
{
    extern __shared__ __nv_bfloat16 smb[];
    const int tid  = threadIdx.x;
    const int wid  = tid >> 5;
    const int lane = tid & 31;
    const int g    = lane >> 2;
    const int tig  = lane & 3;
    const int wm   = wid >> 2;
    const int wn   = wid & 3;
    const int m0 = blockIdx.y * 128;
    const int n0 = blockIdx.x * 128;

    const int a_lrow = lane & 15;
    const int a_koff = (lane >> 4) * 8;
    const int b_nrow = (lane >> 4) * 8 + (lane & 7);
    const int b_koff = ((lane >> 3) & 1) * 8;

    const uint32_t sb = s2u(smb);

    auto load_stage = [&](int s, int b) {
        const uint32_t abase = sb + (uint32_t)b * BH_STAGE_BYTES;
        const uint32_t bbase = abase + BH_A_BYTES;
        const __nv_bfloat16* Ag = A + (size_t)m0 * K + s * 32;
        const __nv_bfloat16* Wg = WT + (size_t)n0 * K + s * 32;
#pragma unroll
        for (int i = 0; i < 2; i++) {
            int c = tid + i * 256;
            int row = c >> 2, k4 = c & 3;
            cp16(abase + row * 80 + k4 * 16, Ag + (size_t)row * K + k4 * 8);
        }
#pragma unroll
        for (int i = 0; i < 2; i++) {
            int c = tid + i * 256;
            int row = c >> 2, k4 = c & 3;
            cp16(bbase + row * 80 + k4 * 16, Wg + (size_t)row * K + k4 * 8);
        }
        asm volatile("cp.async.commit_group;" ::: "memory");
    };

    float acc[4][4][4];
#pragma unroll
    for (int mi = 0; mi < 4; mi++)
#pragma unroll
        for (int ni = 0; ni < 4; ni++)
#pragma unroll
            for (int t = 0; t < 4; t++) acc[mi][ni][t] = 0.f;

    const int NS = K / 32;
    load_stage(0, 0);

    for (int s = 0; s < NS; s++) {
        const int buf = s & 1;
        if (s + 1 < NS) {
            load_stage(s + 1, buf ^ 1);
            asm volatile("cp.async.wait_group 1;" ::: "memory");
        } else {
            asm volatile("cp.async.wait_group 0;" ::: "memory");
        }
        __syncthreads();

        const uint32_t As_u = sb + (uint32_t)buf * BH_STAGE_BYTES;
        const uint32_t Bs_u = As_u + BH_A_BYTES;

#pragma unroll
        for (int ks = 0; ks < 2; ks++) {
            uint32_t af[4][4];
#pragma unroll
            for (int mi = 0; mi < 4; mi++)
                ldsm_x4(af[mi], As_u +
                    (uint32_t)((wm * 64 + mi * 16 + a_lrow) * BH_LD + ks * 16 + a_koff) * 2);
            uint32_t bfr[4][2];
#pragma unroll
            for (int ni = 0; ni < 4; ni += 2) {
                uint32_t t4[4];
                ldsm_x4(t4, Bs_u +
                    (uint32_t)((wn * 32 + ni * 8 + b_nrow) * BH_LD + ks * 16 + b_koff) * 2);
                bfr[ni][0] = t4[0]; bfr[ni][1] = t4[1];
                bfr[ni + 1][0] = t4[2]; bfr[ni + 1][1] = t4[3];
            }
#pragma unroll
            for (int mi = 0; mi < 4; mi++)
#pragma unroll
                for (int ni = 0; ni < 4; ni++)
                    mma_bf16(acc[mi][ni], af[mi], bfr[ni]);
        }
        __syncthreads();
    }

#pragma unroll
    for (int mi = 0; mi < 4; mi++) {
        const int r0 = m0 + wm * 64 + mi * 16 + g;
#pragma unroll
        for (int ni = 0; ni < 4; ni++) {
            const int col = n0 + wn * 32 + ni * 8 + tig * 2;
            const float bx = bias[col], by = bias[col + 1];
#pragma unroll
            for (int hh = 0; hh < 2; hh++) {
                const int row = r0 + hh * 8;
                float cx = acc[mi][ni][hh * 2 + 0] + bx;
                float cy = acc[mi][ni][hh * 2 + 1] + by;
                if (ACT == 1) { cx = gelu_exact(cx); cy = gelu_exact(cy); }
                if (OUTBF) {
                    __nv_bfloat162 p = __floats2bfloat162_rn(cx, cy);
                    *(__nv_bfloat162*)((__nv_bfloat16*)Cout + (size_t)row * N + col) = p;
                } else {
                    *(float2*)((float*)Cout + (size_t)row * N + col) = make_float2(cx, cy);
                }
            }
        }
    }
}

// ------------- weight transposes ---------------------------------------------
__global__ void wt_bf16_kernel(const float* __restrict__ W,
                               __nv_bfloat16* __restrict__ WT, int K, int N) {
    __shared__ float t[32][33];
    const int n0 = blockIdx.x * 32, k0 = blockIdx.y * 32;
    const int tx = threadIdx.x, ty = threadIdx.y;
#pragma unroll
    for (int j = 0; j < 4; j++)
        t[ty + j * 8][tx] = W[(size_t)(k0 + ty + j * 8) * N + n0 + tx];
    __syncthreads();
#pragma unroll
    for (int j = 0; j < 4; j++)
        WT[(size_t)(n0 + ty + j * 8) * K + k0 + tx] = __float2bfloat16(t[tx][ty + j * 8]);
}

__global__ void wt_f32_kernel(const float* __restrict__ W,
                              float* __restrict__ WT, int K, int N) {
    __shared__ float t[32][33];
    const int n0 = blockIdx.x * 32, k0 = blockIdx.y * 32;
    const int tx = threadIdx.x, ty = threadIdx.y;
#pragma unroll
    for (int j = 0; j < 4; j++)
        t[ty + j * 8][tx] = W[(size_t)(k0 + ty + j * 8) * N + n0 + tx];
    __syncthreads();
#pragma unroll
    for (int j = 0; j < 4; j++)
        WT[(size_t)(n0 + ty + j * 8) * K + k0 + tx] = t[tx][ty + j * 8];
}

// ============== adapter-down GEMM: N=64, relu (unchanged R9) ==================
#define AD_B_LD 68
#define AD_STAGE_F (128 * A_LD + 32 * AD_B_LD)
#define AD_SMEM (2 * AD_STAGE_F * 4)

__global__ __launch_bounds__(256) void adapter_down(
    const float* __restrict__ A, const float* __restrict__ W,
    const float* __restrict__ bias, float* __restrict__ C, int K)
{
    extern __shared__ float smem[];
    const int tid  = threadIdx.x;
    const int wid  = tid >> 5;
    const int lane = tid & 31;
    const int g    = lane >> 2;
    const int tig  = lane & 3;
    const int wm   = wid >> 1;
    const int wn   = wid & 1;
    const int m0   = blockIdx.x * 128;

    const int a_lrow = lane & 15;
    const int a_koff = (lane >> 4) * 4;
    const uint32_t sb = s2u(smem);

    auto load_stage = [&](int s, int b) {
        const uint32_t abase = sb + (uint32_t)(b * AD_STAGE_F) * 4;
        const uint32_t bbase = abase + 128 * A_LD * 4;
        const float* Ag = A + (size_t)m0 * K + s * 32;
        const float* Wg = W + (size_t)(s * 32) * A_DIM;
#pragma unroll
        for (int i = 0; i < 4; i++) {
            int c = tid + i * 256;
            int row = c >> 3, k4 = c & 7;
            cp16(abase + row * (A_LD * 4) + k4 * 16, Ag + (size_t)row * K + k4 * 4);
        }
#pragma unroll
        for (int i = 0; i < 2; i++) {
            int c = tid + i * 256;
            int kr = c >> 4, n4 = c & 15;
            cp16(bbase + kr * (AD_B_LD * 4) + n4 * 16, Wg + (size_t)kr * A_DIM + n4 * 4);
        }
        asm volatile("cp.async.commit_group;" ::: "memory");
    };

    float acc[2][4][4];
#pragma unroll
    for (int mi = 0; mi < 2; mi++)
#pragma unroll
        for (int ni = 0; ni < 4; ni++)
#pragma unroll
            for (int t = 0; t < 4; t++) acc[mi][ni][t] = 0.f;

    const int NS = K / 32;
    load_stage(0, 0);

    for (int s = 0; s < NS; s++) {
        const int buf = s & 1;
        if (s + 1 < NS) {
            load_stage(s + 1, buf ^ 1);
            asm volatile("cp.async.wait_group 1;" ::: "memory");
        } else {
            asm volatile("cp.async.wait_group 0;" ::: "memory");
        }
        __syncthreads();

        const uint32_t As_u = sb + (uint32_t)(buf * AD_STAGE_F) * 4;
        const float* Bs = smem + buf * AD_STAGE_F + 128 * A_LD;

#pragma unroll
        for (int ks = 0; ks < 4; ks++) {
            uint32_t afr[2][4];
#pragma unroll
            for (int mi = 0; mi < 2; mi++) {
                ldsm_x4(afr[mi], As_u +
                    (uint32_t)((wm * 32 + mi * 16 + a_lrow) * A_LD + ks * 8 + a_koff) * 4);
            }
            uint32_t bfr[4][2];
#pragma unroll
            for (int ni = 0; ni < 4; ni++) {
                const float* p = Bs + (ks * 8 + tig) * AD_B_LD + wn * 32 + ni * 8 + g;
                bfr[ni][0] = f2tf32(p[0]);
                bfr[ni][1] = f2tf32(p[4 * AD_B_LD]);
            }
#pragma unroll
            for (int mi = 0; mi < 2; mi++)
#pragma unroll
                for (int ni = 0; ni < 4; ni++)
                    mma_tf32(acc[mi][ni], afr[mi], bfr[ni]);
        }
        __syncthreads();
    }

#pragma unroll
    for (int mi = 0; mi < 2; mi++) {
        const int r0 = m0 + wm * 32 + mi * 16 + g;
#pragma unroll
        for (int ni = 0; ni < 4; ni++) {
            const int col = wn * 32 + ni * 8 + tig * 2;
            const float bx = bias[col], by = bias[col + 1];
#pragma unroll
            for (int hh = 0; hh < 2; hh++) {
                const int row = r0 + hh * 8;
                float cx = fmaxf(acc[mi][ni][hh * 2 + 0] + bx, 0.f);
                float cy = fmaxf(acc[mi][ni][hh * 2 + 1] + by, 0.f);
                *(float2*)(C + (size_t)row * A_DIM + col) = make_float2(cx, cy);
            }
        }
    }
}

// ---------------- LayerNorm kernels -------------------------------------------
__global__ __launch_bounds__(256) void ln_kernel(const float* __restrict__ x,
                                                 const float* __restrict__ g,
                                                 const float* __restrict__ b,
                                                 float* __restrict__ out) {
    const int warp = threadIdx.x >> 5, lane = threadIdx.x & 31;
    const int row = blockIdx.x * 8 + warp;
    const float4* xr = (const float4*)(x + (size_t)row * C_DIM);

    float4 v[8];
    float s = 0.f;
#pragma unroll
    for (int i = 0; i < 8; i++) {
        v[i] = xr[i * 32 + lane];
        s += v[i].x + v[i].y + v[i].z + v[i].w;
    }
#pragma unroll
    for (int off = 16; off > 0; off >>= 1)
        s += __shfl_xor_sync(0xFFFFFFFF, s, off);
    const float mean = s * (1.0f / 1024.0f);

    float sq = 0.f;
#pragma unroll
    for (int i = 0; i < 8; i++) {
        float dx = v[i].x - mean, dy = v[i].y - mean,
              dz = v[i].z - mean, dw = v[i].w - mean;
        sq += dx * dx + dy * dy + dz * dz + dw * dw;
    }
#pragma unroll
    for (int off = 16; off > 0; off >>= 1)
        sq += __shfl_xor_sync(0xFFFFFFFF, sq, off);
    const float inv = rsqrtf(sq * (1.0f / 1024.0f) + 1e-5f);

    float4* orow = (float4*)(out + (size_t)row * C_DIM);
    const float4* gv = (const float4*)g;
    const float4* bv = (const float4*)b;
#pragma unroll
    for (int i = 0; i < 8; i++) {
        const int c = i * 32 + lane;
        float4 gg = gv[c], bb = bv[c], o;
        o.x = (v[i].x - mean) * inv * gg.x + bb.x;
        o.y = (v[i].y - mean) * inv * gg.y + bb.y;
        o.z = (v[i].z - mean) * inv * gg.z + bb.z;
        o.w = (v[i].w - mean) * inv * gg.w + bb.w;
        orow[c] = o;
    }
}

__global__ __launch_bounds__(256) void ln_bf16_kernel(const float* __restrict__ x,
                                                      const float* __restrict__ g,
                                                      const float* __restrict__ b,
                                                      __nv_bfloat16* __restrict__ out) {
    const int warp = threadIdx.x >> 5, lane = threadIdx.x & 31;
    const int row = blockIdx.x * 8 + warp;
    const float4* xr = (const float4*)(x + (size_t)row * C_DIM);

    float4 v[8];
    float s = 0.f;
#pragma unroll
    for (int i = 0; i < 8; i++) {
        v[i] = xr[i * 32 + lane];
        s += v[i].x + v[i].y + v[i].z + v[i].w;
    }
#pragma unroll
    for (int off = 16; off > 0; off >>= 1)
        s += __shfl_xor_sync(0xFFFFFFFF, s, off);
    const float mean = s * (1.0f / 1024.0f);

    float sq = 0.f;
#pragma unroll
    for (int i = 0; i < 8; i++) {
        float dx = v[i].x - mean, dy = v[i].y - mean,
              dz = v[i].z - mean, dw = v[i].w - mean;
        sq += dx * dx + dy * dy + dz * dz + dw * dw;
    }
#pragma unroll
    for (int off = 16; off > 0; off >>= 1)
        sq += __shfl_xor_sync(0xFFFFFFFF, sq, off);
    const float inv = rsqrtf(sq * (1.0f / 1024.0f) + 1e-5f);

    __nv_bfloat162* orow = (__nv_bfloat162*)(out + (size_t)row * C_DIM);
    const float4* gv = (const float4*)g;
    const float4* bv = (const float4*)b;
#pragma unroll
    for (int i = 0; i < 8; i++) {
        const int c = i * 32 + lane;
        float4 gg = gv[c], bb = bv[c];
        float ox = (v[i].x - mean) * inv * gg.x + bb.x;
        float oy = (v[i].y - mean) * inv * gg.y + bb.y;
        float oz = (v[i].z - mean) * inv * gg.z + bb.z;
        float ow = (v[i].w - mean) * inv * gg.w + bb.w;
        orow[c * 2]     = __floats2bfloat162_rn(ox, oy);
        orow[c * 2 + 1] = __floats2bfloat162_rn(oz, ow);
    }
}

// ================= Flash attention (unchanged R9) =============================
#define ATT_LD 68
#define ATT_QT 128
#define ATT_SMEM ((ATT_QT + 64 + 64 + ATT_QT) * ATT_LD * 4)

__global__ __launch_bounds__(128) void attn_mma(const float* __restrict__ q,
                                                const float* __restrict__ k,
                                                const float* __restrict__ v,
                                                float* __restrict__ y) {
    extern __shared__ float sm[];
    float* Qs = sm;
    float* Ks = Qs + ATT_QT * ATT_LD;
    float* Vt = Ks + 64 * ATT_LD;

    const int bh = blockIdx.x;
    const int b = bh >> 4, h = bh & 15;
    const int qb = (gridDim.y - 1) - blockIdx.y;
    const int q0 = qb * ATT_QT;
    const int tid = threadIdx.x;
    const int w = tid >> 5, lane = tid & 31;
    const int g = lane >> 2, tig = lane & 3;

    const int a_lrow = lane & 15;
    const int a_koff = (lane >> 4) * 4;
    const int b_tile = lane >> 4;
    const int b_lrow = lane & 7;
    const int b_koff = ((lane >> 3) & 1) * 4;

    const uint32_t sb   = s2u(sm);
    const uint32_t Qs_u = sb;
    const uint32_t Ks_u = sb + (uint32_t)(ATT_QT * ATT_LD) * 4;
    const uint32_t Vt_u = Ks_u + (uint32_t)(64 * ATT_LD) * 4;
    const uint32_t Ps_u = Vt_u + (uint32_t)(64 * ATT_LD) * 4;
    float* Ps = Vt + 64 * ATT_LD;

    const float* qp = q + (size_t)b * T_LEN * C_DIM + h * HDIM;
    const float* kp = k + (size_t)b * T_LEN * C_DIM + h * HDIM;
    const float* vp = v + (size_t)b * T_LEN * C_DIM + h * HDIM;

    {
        const float* src = qp + (size_t)(q0 + tid) * C_DIM;
        float* dst = Qs + tid * ATT_LD;
#pragma unroll
        for (int i = 0; i < 16; i++) {
            float4 t = *(const float4*)(src + i * 4);
            t.x *= 0.125f; t.y *= 0.125f; t.z *= 0.125f; t.w *= 0.125f;
            *(float4*)(dst + i * 4) = t;
        }
    }

    float of[2][8][4];
#pragma unroll
    for (int mi = 0; mi < 2; mi++)
#pragma unroll
        for (int dc = 0; dc < 8; dc++)
#pragma unroll
            for (int t = 0; t < 4; t++) of[mi][dc][t] = 0.f;
    float mrow[2][2] = {{-1e30f, -1e30f}, {-1e30f, -1e30f}};
    float lrow[2][2] = {{0.f, 0.f}, {0.f, 0.f}};

    const int kb_max = 2 * qb + 1;
    const int wmaxrow = q0 + w * 32 + 31;

    for (int kb = 0; kb <= kb_max; kb++) {
        __syncthreads();
        {
            const int r = tid >> 1, s0 = (tid & 1) * 32;
            const float* ks = kp + (size_t)(kb * 64 + r) * C_DIM + s0;
            float* kd = Ks + r * ATT_LD + s0;
#pragma unroll
            for (int i = 0; i < 8; i++)
                *(float4*)(kd + i * 4) = *(const float4*)(ks + i * 4);
            const float* vs = vp + (size_t)(kb * 64 + r) * C_DIM + s0;
#pragma unroll
            for (int i = 0; i < 8; i++) {
                float4 t = *(const float4*)(vs + i * 4);
                const int d = s0 + i * 4;
                Vt[(d + 0) * ATT_LD + r] = t.x;
                Vt[(d + 1) * ATT_LD + r] = t.y;
                Vt[(d + 2) * ATT_LD + r] = t.z;
                Vt[(d + 3) * ATT_LD + r] = t.w;
            }
        }
        __syncthreads();

        if (kb * 64 > wmaxrow) continue;

        float sf[2][8][4];
#pragma unroll
        for (int mi = 0; mi < 2; mi++)
#pragma unroll
            for (int nc = 0; nc < 8; nc++)
#pragma unroll
                for (int t = 0; t < 4; t++) sf[mi][nc][t] = 0.f;
#pragma unroll
        for (int kc = 0; kc < 8; kc++) {
            uint32_t af[2][4];
            ldsm_x4(af[0], Qs_u +
                (uint32_t)((w * 32 + a_lrow) * ATT_LD + kc * 8 + a_koff) * 4);
            ldsm_x4(af[1], Qs_u +
                (uint32_t)((w * 32 + 16 + a_lrow) * ATT_LD + kc * 8 + a_koff) * 4);
#pragma unroll
            for (int nc = 0; nc < 8; nc += 2) {
                uint32_t bf[4];
                ldsm_x4(bf, Ks_u +
                    (uint32_t)(((nc + b_tile) * 8 + b_lrow) * ATT_LD + kc * 8 + b_koff) * 4);
                mma_tf32(sf[0][nc],     af[0], bf);
                mma_tf32(sf[1][nc],     af[1], bf);
                mma_tf32(sf[0][nc + 1], af[0], bf + 2);
                mma_tf32(sf[1][nc + 1], af[1], bf + 2);
            }
        }

#pragma unroll
        for (int mi = 0; mi < 2; mi++) {
            const int base = q0 + w * 32 + mi * 16;
            if (kb * 64 + 63 > base) {
                const int r0 = base + g, r1 = base + g + 8;
#pragma unroll
                for (int nc = 0; nc < 8; nc++) {
                    const int j0 = kb * 64 + nc * 8 + 2 * tig;
                    if (j0 > r0)     sf[mi][nc][0] = -1e30f;
                    if (j0 + 1 > r0) sf[mi][nc][1] = -1e30f;
                    if (j0 > r1)     sf[mi][nc][2] = -1e30f;
                    if (j0 + 1 > r1) sf[mi][nc][3] = -1e30f;
                }
            }
            float ml0 = -1e30f, ml1 = -1e30f;
#pragma unroll
            for (int nc = 0; nc < 8; nc++) {
                ml0 = fmaxf(ml0, fmaxf(sf[mi][nc][0], sf[mi][nc][1]));
                ml1 = fmaxf(ml1, fmaxf(sf[mi][nc][2], sf[mi][nc][3]));
            }
            ml0 = fmaxf(ml0, __shfl_xor_sync(0xFFFFFFFF, ml0, 1));
            ml0 = fmaxf(ml0, __shfl_xor_sync(0xFFFFFFFF, ml0, 2));
            ml1 = fmaxf(ml1, __shfl_xor_sync(0xFFFFFFFF, ml1, 1));
            ml1 = fmaxf(ml1, __shfl_xor_sync(0xFFFFFFFF, ml1, 2));

            const float mn0 = fmaxf(mrow[mi][0], ml0);
            const float mn1 = fmaxf(mrow[mi][1], ml1);
            const float al0 = __expf(mrow[mi][0] - mn0);
            const float al1 = __expf(mrow[mi][1] - mn1);
            lrow[mi][0] *= al0; lrow[mi][1] *= al1;
#pragma unroll
            for (int dc = 0; dc < 8; dc++) {
                of[mi][dc][0] *= al0; of[mi][dc][1] *= al0;
                of[mi][dc][2] *= al1; of[mi][dc][3] *= al1;
            }
#pragma unroll
            for (int nc = 0; nc < 8; nc++) {
                sf[mi][nc][0] = __expf(sf[mi][nc][0] - mn0);
                sf[mi][nc][1] = __expf(sf[mi][nc][1] - mn0);
                sf[mi][nc][2] = __expf(sf[mi][nc][2] - mn1);
                sf[mi][nc][3] = __expf(sf[mi][nc][3] - mn1);
                lrow[mi][0] += sf[mi][nc][0] + sf[mi][nc][1];
                lrow[mi][1] += sf[mi][nc][2] + sf[mi][nc][3];
            }
            mrow[mi][0] = mn0; mrow[mi][1] = mn1;

            float* pw = Ps + (w * 32 + mi * 16) * ATT_LD;
#pragma unroll
            for (int nc = 0; nc < 8; nc++) {
                pw[g * ATT_LD + nc * 8 + 2 * tig]           = sf[mi][nc][0];
                pw[g * ATT_LD + nc * 8 + 2 * tig + 1]       = sf[mi][nc][1];
                pw[(g + 8) * ATT_LD + nc * 8 + 2 * tig]     = sf[mi][nc][2];
                pw[(g + 8) * ATT_LD + nc * 8 + 2 * tig + 1] = sf[mi][nc][3];
            }
        }
        __syncwarp();

#pragma unroll
        for (int kc = 0; kc < 8; kc++) {
            uint32_t pf[2][4];
            ldsm_x4(pf[0], Ps_u +
                (uint32_t)((w * 32 + a_lrow) * ATT_LD + kc * 8 + a_koff) * 4);
            ldsm_x4(pf[1], Ps_u +
                (uint32_t)((w * 32 + 16 + a_lrow) * ATT_LD + kc * 8 + a_koff) * 4);
#pragma unroll
            for (int dc = 0; dc < 8; dc += 2) {
                uint32_t bf[4];
                ldsm_x4(bf, Vt_u +
                    (uint32_t)(((dc + b_tile) * 8 + b_lrow) * ATT_LD + kc * 8 + b_koff) * 4);
                mma_tf32(of[0][dc],     pf[0], bf);
                mma_tf32(of[1][dc],     pf[1], bf);
                mma_tf32(of[0][dc + 1], pf[0], bf + 2);
                mma_tf32(of[1][dc + 1], pf[1], bf + 2);
            }
        }
        __syncwarp();
    }

#pragma unroll
    for (int mi = 0; mi < 2; mi++) {
        float l0 = lrow[mi][0], l1 = lrow[mi][1];
        l0 += __shfl_xor_sync(0xFFFFFFFF, l0, 1);
        l0 += __shfl_xor_sync(0xFFFFFFFF, l0, 2);
        l1 += __shfl_xor_sync(0xFFFFFFFF, l1, 1);
        l1 += __shfl_xor_sync(0xFFFFFFFF, l1, 2);
        const float inv0 = 1.f / l0, inv1 = 1.f / l1;

        float* yp = y + ((size_t)b * T_LEN + q0 + w * 32 + mi * 16) * C_DIM + h * HDIM;
#pragma unroll
        for (int dc = 0; dc < 8; dc++) {
            const int col = dc * 8 + 2 * tig;
            *(float2*)(yp + (size_t)g * C_DIM + col) =
                make_float2(of[mi][dc][0] * inv0, of[mi][dc][1] * inv0);
            *(float2*)(yp + (size_t)(g + 8) * C_DIM + col) =
                make_float2(of[mi][dc][2] * inv1, of[mi][dc][3] * inv1);
        }
    }
}

// -----------------------------------------------------------------------------
extern "C" void kernel_launch(void* const* d_in, const int* in_sizes, int n_in,
                              void* d_out, int out_size) {
    const float* x     = (const float*)d_in[0];
    const float* ln1_g = (const float*)d_in[1];
    const float* ln1_b = (const float*)d_in[2];
    const float* ln2_g = (const float*)d_in[3];
    const float* ln2_b = (const float*)d_in[4];
    const float* ln3_g = (const float*)d_in[5];
    const float* ln3_b = (const float*)d_in[6];
    const float* wq = (const float*)d_in[7];   const float* bq = (const float*)d_in[8];
    const float* wk = (const float*)d_in[9];   const float* bk = (const float*)d_in[10];
    const float* wv = (const float*)d_in[11];  const float* bv = (const float*)d_in[12];
    const float* wo = (const float*)d_in[13];  const float* bo = (const float*)d_in[14];
    const float* w1 = (const float*)d_in[15];  const float* b1 = (const float*)d_in[16];
    const float* w2 = (const float*)d_in[17];  const float* b2 = (const float*)d_in[18];
    const float* wd = (const float*)d_in[19];  const float* bd = (const float*)d_in[20];
    const float* wu = (const float*)d_in[21];  const float* bu = (const float*)d_in[22];
    float* out = (float*)d_out;

    float *h, *q, *k, *v, *y, *hidden, *mlp, *n3, *ad1;
    float *wqt, *wkt, *wvt, *wot;
    __nv_bfloat16 *mb, *ffb, *w1b, *w2b;
    cudaGetSymbolAddress((void**)&h,      g_h);
    cudaGetSymbolAddress((void**)&q,      g_q);
    cudaGetSymbolAddress((void**)&k,      g_k);
    cudaGetSymbolAddress((void**)&v,      g_v);
    cudaGetSymbolAddress((void**)&y,      g_y);
    cudaGetSymbolAddress((void**)&hidden, g_hidden);
    cudaGetSymbolAddress((void**)&mlp,    g_mlp);
    cudaGetSymbolAddress((void**)&n3,     g_n3);
    cudaGetSymbolAddress((void**)&ad1,    g_ad1);
    cudaGetSymbolAddress((void**)&wqt,    g_wqt);
    cudaGetSymbolAddress((void**)&wkt,    g_wkt);
    cudaGetSymbolAddress((void**)&wvt,    g_wvt);
    cudaGetSymbolAddress((void**)&wot,    g_wot);
    cudaGetSymbolAddress((void**)&mb,     g_mb);
    cudaGetSymbolAddress((void**)&ffb,    g_ffb);
    cudaGetSymbolAddress((void**)&w1b,    g_w1b);
    cudaGetSymbolAddress((void**)&w2b,    g_w2b);

    cudaFuncSetAttribute(qkv_gemm, cudaFuncAttributeMaxDynamicSharedMemorySize, tn_smem<4>());
    cudaFuncSetAttribute(tn_gemm<0, 1, 2>, cudaFuncAttributeMaxDynamicSharedMemorySize, tn_smem<2>());
    cudaFuncSetAttribute(tc_gemm<0, 2, 2>, cudaFuncAttributeMaxDynamicSharedMemorySize, gemm_smem<2>());
    cudaFuncSetAttribute(adapter_down, cudaFuncAttributeMaxDynamicSharedMemorySize, AD_SMEM);
    cudaFuncSetAttribute(attn_mma, cudaFuncAttributeMaxDynamicSharedMemorySize, ATT_SMEM);
    cudaFuncSetAttribute(bf16_gemm<1, true>,  cudaFuncAttributeMaxDynamicSharedMemorySize, BH_SMEM);
    cudaFuncSetAttribute(bf16_gemm<0, false>, cudaFuncAttributeMaxDynamicSharedMemorySize, BH_SMEM);

    // Weight conversions/transposes (independent; run first)
    wt_bf16_kernel<<<dim3(FF_DIM / 32, C_DIM / 32), dim3(32, 8)>>>(w1, w1b, C_DIM, FF_DIM);
    wt_bf16_kernel<<<dim3(C_DIM / 32, FF_DIM / 32), dim3(32, 8)>>>(w2, w2b, FF_DIM, C_DIM);
    wt_f32_kernel<<<dim3(C_DIM / 32, C_DIM / 32), dim3(32, 8)>>>(wq, wqt, C_DIM, C_DIM);
    wt_f32_kernel<<<dim3(C_DIM / 32, C_DIM / 32), dim3(32, 8)>>>(wk, wkt, C_DIM, C_DIM);
    wt_f32_kernel<<<dim3(C_DIM / 32, C_DIM / 32), dim3(32, 8)>>>(wv, wvt, C_DIM, C_DIM);
    wt_f32_kernel<<<dim3(C_DIM / 32, C_DIM / 32), dim3(32, 8)>>>(wo, wot, C_DIM, C_DIM);

    // LN1(x), LN3(x)
    ln_kernel<<<M_ROWS / 8, 256>>>(x, ln1_g, ln1_b, h);
    ln_kernel<<<M_ROWS / 8, 256>>>(x, ln3_g, ln3_b, n3);

    // fused QKV projection (tf32, transposed-B all-ldmatrix)
    qkv_gemm<<<dim3(24, 32), 256, tn_smem<4>()>>>(h, wqt, wkt, wvt, bq, bk, bv, q, k, v);

    // Causal attention
    attn_mma<<<dim3(4 * NHEAD, T_LEN / ATT_QT), 128, ATT_SMEM>>>(q, k, v, y);

    // Output projection + residual -> hidden (tf32 transposed-B)
    tn_gemm<0, 1, 2><<<dim3(8, 64), 256, tn_smem<2>()>>>(y, wot, bo, x, nullptr, hidden, C_DIM, C_DIM);

    // adapter-down on ln3(x)
    adapter_down<<<32, 256, AD_SMEM>>>(n3, wd, bd, ad1, C_DIM);

    // MLP on ln2(hidden) — bf16 tensor cores
    ln_bf16_kernel<<<M_ROWS / 8, 256>>>(hidden, ln2_g, ln2_b, mb);
    bf16_gemm<1, true><<<dim3(FF_DIM / 128, M_ROWS / 128), 256, BH_SMEM>>>(
        mb, w1b, b1, ffb, FF_DIM, C_DIM);
    bf16_gemm<0, false><<<dim3(C_DIM / 128, M_ROWS / 128), 256, BH_SMEM>>>(
        ffb, w2b, b2, mlp, C_DIM, FF_DIM);

    // adapter-up + final combine: out = (ad1@wu + bu) + 2*hidden + mlp
    tc_gemm<0, 2, 2><<<dim3(8, 64), 256, gemm_smem<2>()>>>(ad1, wu, bu, hidden, mlp, out, C_DIM, A_DIM);
}

// round 17
// speedup vs baseline: 1.0032x; 1.0032x over previous
#include <cuda_runtime.h>
#include <cuda_bf16.h>
#include <math.h>
#include <stdint.h>

// Shapes
#define M_ROWS 4096   // B*T
#define C_DIM  1024
#define FF_DIM 4096
#define A_DIM  64
#define T_LEN  1024
#define NHEAD  16
#define HDIM   64

// ---------------- scratch (device globals; no allocs allowed) ----------------
__device__ float g_h     [M_ROWS * C_DIM];
__device__ float g_q     [M_ROWS * C_DIM];
__device__ float g_k     [M_ROWS * C_DIM];
__device__ float g_v     [M_ROWS * C_DIM];
__device__ float g_y     [M_ROWS * C_DIM];
__device__ float g_hidden[M_ROWS * C_DIM];
__device__ float g_mlp   [M_ROWS * C_DIM];
__device__ float g_n3    [M_ROWS * C_DIM];
__device__ float g_ad1   [M_ROWS * A_DIM];
__device__ float g_wqt   [C_DIM * C_DIM];          // fp32 transposed weights [N][K]
__device__ float g_wkt   [C_DIM * C_DIM];
__device__ float g_wvt   [C_DIM * C_DIM];
__device__ float g_wot   [C_DIM * C_DIM];
__device__ __nv_bfloat16 g_mb [M_ROWS * C_DIM];    // ln2(hidden) in bf16
__device__ __nv_bfloat16 g_ffb[M_ROWS * FF_DIM];   // gelu(m@w1+b1) in bf16
__device__ __nv_bfloat16 g_w1b[FF_DIM * C_DIM];    // w1^T bf16 [N][K]
__device__ __nv_bfloat16 g_w2b[C_DIM * FF_DIM];    // w2^T bf16 [N][K]

// ======================= helpers ==============================================
__device__ __forceinline__ void cp16(uint32_t dst, const void* src) {
    asm volatile("cp.async.cg.shared.global [%0], [%1], 16;"
                 :: "r"(dst), "l"(src) : "memory");
}
__device__ __forceinline__ uint32_t s2u(const void* p) {
    uint32_t a;
    asm("{ .reg .u64 t; cvta.to.shared.u64 t, %1; cvt.u32.u64 %0, t; }"
        : "=r"(a) : "l"(p));
    return a;
}
// Raw fp32 bits fed to tf32 mma: HW uses top 19 bits (RZ-equivalent).
__device__ __forceinline__ uint32_t f2tf32(float x) { return __float_as_uint(x); }

__device__ __forceinline__ void ldsm_x4(uint32_t* r, uint32_t addr) {
    asm volatile("ldmatrix.sync.aligned.m8n8.x4.shared.b16 {%0,%1,%2,%3}, [%4];"
                 : "=r"(r[0]), "=r"(r[1]), "=r"(r[2]), "=r"(r[3]) : "r"(addr));
}

__device__ __forceinline__ void mma_tf32(float* c, const uint32_t* a, const uint32_t* b) {
    asm volatile(
        "mma.sync.aligned.m16n8k8.row.col.f32.tf32.tf32.f32 "
        "{%0,%1,%2,%3}, {%4,%5,%6,%7}, {%8,%9}, {%0,%1,%2,%3};"
        : "+f"(c[0]), "+f"(c[1]), "+f"(c[2]), "+f"(c[3])
        : "r"(a[0]), "r"(a[1]), "r"(a[2]), "r"(a[3]), "r"(b[0]), "r"(b[1]));
}
__device__ __forceinline__ void mma_bf16(float* c, const uint32_t* a, const uint32_t* b) {
    asm volatile(
        "mma.sync.aligned.m16n8k16.row.col.f32.bf16.bf16.f32 "
        "{%0,%1,%2,%3}, {%4,%5,%6,%7}, {%8,%9}, {%0,%1,%2,%3};"
        : "+f"(c[0]), "+f"(c[1]), "+f"(c[2]), "+f"(c[3])
        : "r"(a[0]), "r"(a[1]), "r"(a[2]), "r"(a[3]), "r"(b[0]), "r"(b[1]));
}
__device__ __forceinline__ float gelu_exact(float x) {
    return 0.5f * x * (1.0f + erff(x * 0.7071067811865476f));
}

// ============ tf32 GEMM, transposed-B ([N][K]) all-ldmatrix core ==============
// A fp32 [M][K], WT fp32 [N][K]. Tile MI*32 x 128. K staged by 32, 2 stages.
#define T_LD 36
#define T_B_STAGE_F (128 * T_LD)    // 4608

template <int MI>
__host__ __device__ constexpr int tn_stage_f() { return MI * 32 * T_LD + T_B_STAGE_F; }
template <int MI>
__host__ __device__ constexpr int tn_smem() { return 2 * tn_stage_f<MI>() * 4; }

// RMODE: 0 none, 1 out += res1, 2 out += 2*res1 + res2
template <int ACT, int RMODE, int MI>
__device__ __forceinline__ void tn_core(
    const float* __restrict__ A, const float* __restrict__ WT,
    const float* __restrict__ bias,
    const float* __restrict__ res1, const float* __restrict__ res2,
    float* __restrict__ C, int N, int K, int m0, int n0, float* smem)
{
    const int A_STAGE_F = MI * 32 * T_LD;
    const int STAGE_F = A_STAGE_F + T_B_STAGE_F;

    const int tid  = threadIdx.x;
    const int wid  = tid >> 5;
    const int lane = tid & 31;
    const int g    = lane >> 2;
    const int tig  = lane & 3;
    const int wm   = wid >> 2;       // 0..1
    const int wn   = wid & 3;        // 0..3

    const int a_lrow = lane & 15;
    const int a_koff = (lane >> 4) * 4;
    const int b_row16 = (lane & 7) + (lane >> 4) * 8;   // 2 n-tiles per x4
    const int b_koff  = ((lane >> 3) & 1) * 4;

    const uint32_t sb = s2u(smem);

    auto load_stage = [&](int s, int b) {
        const uint32_t abase = sb + (uint32_t)(b * STAGE_F) * 4;
        const uint32_t bbase = abase + A_STAGE_F * 4;
        const float* Ag = A + (size_t)m0 * K + s * 32;
        const float* Wg = WT + (size_t)n0 * K + s * 32;
#pragma unroll
        for (int i = 0; i < MI; i++) {
            int c = tid + i * 256;
            int row = c >> 3, k4 = c & 7;
            cp16(abase + row * (T_LD * 4) + k4 * 16,
                 Ag + (size_t)row * K + k4 * 4);
        }
#pragma unroll
        for (int i = 0; i < 4; i++) {
            int c = tid + i * 256;
            int row = c >> 3, k4 = c & 7;
            cp16(bbase + row * (T_LD * 4) + k4 * 16,
                 Wg + (size_t)row * K + k4 * 4);
        }
        asm volatile("cp.async.commit_group;" ::: "memory");
    };

    float acc[MI][4][4];
#pragma unroll
    for (int mi = 0; mi < MI; mi++)
#pragma unroll
        for (int ni = 0; ni < 4; ni++)
#pragma unroll
            for (int t = 0; t < 4; t++) acc[mi][ni][t] = 0.f;

    const int NS = K / 32;
    load_stage(0, 0);

    for (int s = 0; s < NS; s++) {
        const int buf = s & 1;
        if (s + 1 < NS) {
            load_stage(s + 1, buf ^ 1);
            asm volatile("cp.async.wait_group 1;" ::: "memory");
        } else {
            asm volatile("cp.async.wait_group 0;" ::: "memory");
        }
        __syncthreads();

        const uint32_t As_u = sb + (uint32_t)(buf * STAGE_F) * 4;
        const uint32_t Bs_u = As_u + (uint32_t)A_STAGE_F * 4;

#pragma unroll
        for (int ks = 0; ks < 4; ks++) {
            uint32_t afr[MI][4];
#pragma unroll
            for (int mi = 0; mi < MI; mi++) {
                ldsm_x4(afr[mi], As_u +
                    (uint32_t)((wm * (MI * 16) + mi * 16 + a_lrow) * T_LD + ks * 8 + a_koff) * 4);
            }
            uint32_t bfr[4][2];
#pragma unroll
            for (int ni = 0; ni < 4; ni += 2) {
                uint32_t t4[4];
                ldsm_x4(t4, Bs_u +
                    (uint32_t)((wn * 32 + ni * 8 + b_row16) * T_LD + ks * 8 + b_koff) * 4);
                bfr[ni][0] = t4[0];     bfr[ni][1] = t4[1];
                bfr[ni + 1][0] = t4[2]; bfr[ni + 1][1] = t4[3];
            }
#pragma unroll
            for (int mi = 0; mi < MI; mi++)
#pragma unroll
                for (int ni = 0; ni < 4; ni++)
                    mma_tf32(acc[mi][ni], afr[mi], bfr[ni]);
        }
        __syncthreads();
    }

#pragma unroll
    for (int mi = 0; mi < MI; mi++) {
        const int r0 = m0 + wm * (MI * 16) + mi * 16 + g;
#pragma unroll
        for (int ni = 0; ni < 4; ni++) {
            const int col = n0 + wn * 32 + ni * 8 + tig * 2;
            const float bx = bias[col], by = bias[col + 1];
#pragma unroll
            for (int hh = 0; hh < 2; hh++) {
                const int row = r0 + hh * 8;
                float cx = acc[mi][ni][hh * 2 + 0] + bx;
                float cy = acc[mi][ni][hh * 2 + 1] + by;
                if (ACT == 1) { cx = gelu_exact(cx); cy = gelu_exact(cy); }
                if (RMODE == 1) {
                    cx += res1[(size_t)row * N + col];
                    cy += res1[(size_t)row * N + col + 1];
                } else if (RMODE == 2) {
                    const float2 h2 = *(const float2*)(res1 + (size_t)row * N + col);
                    const float2 m2 = *(const float2*)(res2 + (size_t)row * N + col);
                    cx += 2.f * h2.x + m2.x;
                    cy += 2.f * h2.y + m2.y;
                }
                *(float2*)(C + (size_t)row * N + col) = make_float2(cx, cy);
            }
        }
    }
}

template <int ACT, int RMODE, int MI>
__global__ __launch_bounds__(256) void tn_gemm(
    const float* __restrict__ A, const float* __restrict__ WT,
    const float* __restrict__ bias,
    const float* __restrict__ res1, const float* __restrict__ res2,
    float* __restrict__ C, int N, int K)
{
    extern __shared__ float smem[];
    tn_core<ACT, RMODE, MI>(A, WT, bias, res1, res2, C, N, K,
                            blockIdx.y * (MI * 32), blockIdx.x * 128, smem);
}

// fused QKV (transposed weights)
__global__ __launch_bounds__(256) void qkv_gemm(
    const float* __restrict__ A,
    const float* __restrict__ wqt, const float* __restrict__ wkt, const float* __restrict__ wvt,
    const float* __restrict__ bq, const float* __restrict__ bk, const float* __restrict__ bv,
    float* __restrict__ q, float* __restrict__ k, float* __restrict__ v)
{
    extern __shared__ float smem[];
    const int mat = blockIdx.x >> 3;
    const int n0  = (blockIdx.x & 7) * 128;
    const float* W = (mat == 0) ? wqt : (mat == 1) ? wkt : wvt;
    const float* B = (mat == 0) ? bq  : (mat == 1) ? bk  : bv;
    float* C       = (mat == 0) ? q   : (mat == 1) ? k   : v;
    tn_core<0, 0, 4>(A, W, B, nullptr, nullptr, C, C_DIM, C_DIM,
                     blockIdx.y * 128, n0, smem);
}

// ============ legacy tf32 GEMM (B row-major) — adapter-up only ================
#define A_LD 36
#define B_LD 132
#define B_STAGE_F (32 * B_LD)

template <int MI>
__host__ __device__ constexpr int gemm_smem() { return 2 * (MI * 32 * A_LD + B_STAGE_F) * 4; }

template <int ACT, int RMODE, int MI>
__global__ __launch_bounds__(256) void tc_gemm(
    const float* __restrict__ A, const float* __restrict__ W,
    const float* __restrict__ bias,
    const float* __restrict__ res1, const float* __restrict__ res2,
    float* __restrict__ C, int N, int K)
{
    extern __shared__ float smem[];
    const int A_STAGE_F = MI * 32 * A_LD;
    const int STAGE_F = A_STAGE_F + B_STAGE_F;
    const int m0 = blockIdx.y * (MI * 32);
    const int n0 = blockIdx.x * 128;

    const int tid  = threadIdx.x;
    const int wid  = tid >> 5;
    const int lane = tid & 31;
    const int g    = lane >> 2;
    const int tig  = lane & 3;
    const int wm   = wid >> 2;
    const int wn   = wid & 3;
    const int a_lrow = lane & 15;
    const int a_koff = (lane >> 4) * 4;
    const uint32_t sb = s2u(smem);

    auto load_stage = [&](int s, int b) {
        const uint32_t abase = sb + (uint32_t)(b * STAGE_F) * 4;
        const uint32_t bbase = abase + A_STAGE_F * 4;
        const float* Ag = A + (size_t)m0 * K + s * 32;
        const float* Wg = W + (size_t)(s * 32) * N + n0;
#pragma unroll
        for (int i = 0; i < MI; i++) {
            int c = tid + i * 256;
            int row = c >> 3, k4 = c & 7;
            cp16(abase + row * (A_LD * 4) + k4 * 16, Ag + (size_t)row * K + k4 * 4);
        }
#pragma unroll
        for (int i = 0; i < 4; i++) {
            int c = tid + i * 256;
            int kr = c >> 5, n4 = c & 31;
            cp16(bbase + kr * (B_LD * 4) + n4 * 16, Wg + (size_t)kr * N + n4 * 4);
        }
        asm volatile("cp.async.commit_group;" ::: "memory");
    };

    float acc[MI][4][4];
#pragma unroll
    for (int mi = 0; mi < MI; mi++)
#pragma unroll
        for (int ni = 0; ni < 4; ni++)
#pragma unroll
            for (int t = 0; t < 4; t++) acc[mi][ni][t] = 0.f;

    const int NS = K / 32;
    load_stage(0, 0);

    for (int s = 0; s < NS; s++) {
        const int buf = s & 1;
        if (s + 1 < NS) {
            load_stage(s + 1, buf ^ 1);
            asm volatile("cp.async.wait_group 1;" ::: "memory");
        } else {
            asm volatile("cp.async.wait_group 0;" ::: "memory");
        }
        __syncthreads();

        const uint32_t As_u = sb + (uint32_t)(buf * STAGE_F) * 4;
        const float* Bs = smem + buf * STAGE_F + A_STAGE_F;

#pragma unroll
        for (int ks = 0; ks < 4; ks++) {
            uint32_t afr[MI][4];
#pragma unroll
            for (int mi = 0; mi < MI; mi++) {
                ldsm_x4(afr[mi], As_u +
                    (uint32_t)((wm * (MI * 16) + mi * 16 + a_lrow) * A_LD + ks * 8 + a_koff) * 4);
            }
            uint32_t bfr[4][2];
#pragma unroll
            for (int ni = 0; ni < 4; ni++) {
                const float* p = Bs + (ks * 8 + tig) * B_LD + wn * 32 + ni * 8 + g;
                bfr[ni][0] = f2tf32(p[0]);
                bfr[ni][1] = f2tf32(p[4 * B_LD]);
            }
#pragma unroll
            for (int mi = 0; mi < MI; mi++)
#pragma unroll
                for (int ni = 0; ni < 4; ni++)
                    mma_tf32(acc[mi][ni], afr[mi], bfr[ni]);
        }
        __syncthreads();
    }

#pragma unroll
    for (int mi = 0; mi < MI; mi++) {
        const int r0 = m0 + wm * (MI * 16) + mi * 16 + g;
#pragma unroll
        for (int ni = 0; ni < 4; ni++) {
            const int col = n0 + wn * 32 + ni * 8 + tig * 2;
            const float bx = bias[col], by = bias[col + 1];
#pragma unroll
            for (int hh = 0; hh < 2; hh++) {
                const int row = r0 + hh * 8;
                float cx = acc[mi][ni][hh * 2 + 0] + bx;
                float cy = acc[mi][ni][hh * 2 + 1] + by;
                if (ACT == 1) { cx = gelu_exact(cx); cy = gelu_exact(cy); }
                if (RMODE == 1) {
                    cx += res1[(size_t)row * N + col];
                    cy += res1[(size_t)row * N + col + 1];
                } else if (RMODE == 2) {
                    const float2 h2 = *(const float2*)(res1 + (size_t)row * N + col);
                    const float2 m2 = *(const float2*)(res2 + (size_t)row * N + col);
                    cx += 2.f * h2.x + m2.x;
                    cy += 2.f * h2.y + m2.y;
                }
                *(float2*)(C + (size_t)row * N + col) = make_float2(cx, cy);
            }
        }
    }
}

// ==================== bf16 m16n8k16 GEMM (MLP path) ==========================
#define BH_LD 40
#define BH_A_BYTES (128 * BH_LD * 2)
#define BH_STAGE_BYTES (2 * BH_A_BYTES)
#define BH_SMEM (2 * BH_STAGE_BYTES)

template <int ACT, bool OUTBF>
__global__ __launch_bounds__(256) void bf16_gemm(
    const __nv_bfloat16* __restrict__ A, const __nv_bfloat16* __restrict__ WT,
    const float* __restrict__ bias, void* __restrict__ Cout, int N, int K)
{
    extern __shared__ __nv_bfloat16 smb[];
    const int tid  = threadIdx.x;
    const int wid  = tid >> 5;
    const int lane = tid & 31;
    const int g    = lane >> 2;
    const int tig  = lane & 3;
    const int wm   = wid >> 2;
    const int wn   = wid & 3;
    const int m0 = blockIdx.y * 128;
    const int n0 = blockIdx.x * 128;

    const int a_lrow = lane & 15;
    const int a_koff = (lane >> 4) * 8;
    const int b_nrow = (lane >> 4) * 8 + (lane & 7);
    const int b_koff = ((lane >> 3) & 1) * 8;

    const uint32_t sb = s2u(smb);

    auto load_stage = [&](int s, int b) {
        const uint32_t abase = sb + (uint32_t)b * BH_STAGE_BYTES;
        const uint32_t bbase = abase + BH_A_BYTES;
        const __nv_bfloat16* Ag = A + (size_t)m0 * K + s * 32;
        const __nv_bfloat16* Wg = WT + (size_t)n0 * K + s * 32;
#pragma unroll
        for (int i = 0; i < 2; i++) {
            int c = tid + i * 256;
            int row = c >> 2, k4 = c & 3;
            cp16(abase + row * 80 + k4 * 16, Ag + (size_t)row * K + k4 * 8);
        }
#pragma unroll
        for (int i = 0; i < 2; i++) {
            int c = tid + i * 256;
            int row = c >> 2, k4 = c & 3;
            cp16(bbase + row * 80 + k4 * 16, Wg + (size_t)row * K + k4 * 8);
        }
        asm volatile("cp.async.commit_group;" ::: "memory");
    };

    float acc[4][4][4];
#pragma unroll
    for (int mi = 0; mi < 4; mi++)
#pragma unroll
        for (int ni = 0; ni < 4; ni++)
#pragma unroll
            for (int t = 0; t < 4; t++) acc[mi][ni][t] = 0.f;

    const int NS = K / 32;
    load_stage(0, 0);

    for (int s = 0; s < NS; s++) {
        const int buf = s & 1;
        if (s + 1 < NS) {
            load_stage(s + 1, buf ^ 1);
            asm volatile("cp.async.wait_group 1;" ::: "memory");
        } else {
            asm volatile("cp.async.wait_group 0;" ::: "memory");
        }
        __syncthreads();

        const uint32_t As_u = sb + (uint32_t)buf * BH_STAGE_BYTES;
        const uint32_t Bs_u = As_u + BH_A_BYTES;

#pragma unroll
        for (int ks = 0; ks < 2; ks++) {
            uint32_t af[4][4];
#pragma unroll
            for (int mi = 0; mi < 4; mi++)
                ldsm_x4(af[mi], As_u +
                    (uint32_t)((wm * 64 + mi * 16 + a_lrow) * BH_LD + ks * 16 + a_koff) * 2);
            uint32_t bfr[4][2];
#pragma unroll
            for (int ni = 0; ni < 4; ni += 2) {
                uint32_t t4[4];
                ldsm_x4(t4, Bs_u +
                    (uint32_t)((wn * 32 + ni * 8 + b_nrow) * BH_LD + ks * 16 + b_koff) * 2);
                bfr[ni][0] = t4[0]; bfr[ni][1] = t4[1];
                bfr[ni + 1][0] = t4[2]; bfr[ni + 1][1] = t4[3];
            }
#pragma unroll
            for (int mi = 0; mi < 4; mi++)
#pragma unroll
                for (int ni = 0; ni < 4; ni++)
                    mma_bf16(acc[mi][ni], af[mi], bfr[ni]);
        }
        __syncthreads();
    }

#pragma unroll
    for (int mi = 0; mi < 4; mi++) {
        const int r0 = m0 + wm * 64 + mi * 16 + g;
#pragma unroll
        for (int ni = 0; ni < 4; ni++) {
            const int col = n0 + wn * 32 + ni * 8 + tig * 2;
            const float bx = bias[col], by = bias[col + 1];
#pragma unroll
            for (int hh = 0; hh < 2; hh++) {
                const int row = r0 + hh * 8;
                float cx = acc[mi][ni][hh * 2 + 0] + bx;
                float cy = acc[mi][ni][hh * 2 + 1] + by;
                if (ACT == 1) { cx = gelu_exact(cx); cy = gelu_exact(cy); }
                if (OUTBF) {
                    __nv_bfloat162 p = __floats2bfloat162_rn(cx, cy);
                    *(__nv_bfloat162*)((__nv_bfloat16*)Cout + (size_t)row * N + col) = p;
                } else {
                    *(float2*)((float*)Cout + (size_t)row * N + col) = make_float2(cx, cy);
                }
            }
        }
    }
}

// ------------- weight transposes ---------------------------------------------
__global__ void wt_bf16_kernel(const float* __restrict__ W,
                               __nv_bfloat16* __restrict__ WT, int K, int N) {
    __shared__ float t[32][33];
    const int n0 = blockIdx.x * 32, k0 = blockIdx.y * 32;
    const int tx = threadIdx.x, ty = threadIdx.y;
#pragma unroll
    for (int j = 0; j < 4; j++)
        t[ty + j * 8][tx] = W[(size_t)(k0 + ty + j * 8) * N + n0 + tx];
    __syncthreads();
#pragma unroll
    for (int j = 0; j < 4; j++)
        WT[(size_t)(n0 + ty + j * 8) * K + k0 + tx] = __float2bfloat16(t[tx][ty + j * 8]);
}

__global__ void wt_f32_kernel(const float* __restrict__ W,
                              float* __restrict__ WT, int K, int N) {
    __shared__ float t[32][33];
    const int n0 = blockIdx.x * 32, k0 = blockIdx.y * 32;
    const int tx = threadIdx.x, ty = threadIdx.y;
#pragma unroll
    for (int j = 0; j < 4; j++)
        t[ty + j * 8][tx] = W[(size_t)(k0 + ty + j * 8) * N + n0 + tx];
    __syncthreads();
#pragma unroll
    for (int j = 0; j < 4; j++)
        WT[(size_t)(n0 + ty + j * 8) * K + k0 + tx] = t[tx][ty + j * 8];
}

// ============== adapter-down GEMM: N=64, relu (unchanged R9) ==================
#define AD_B_LD 68
#define AD_STAGE_F (128 * A_LD + 32 * AD_B_LD)
#define AD_SMEM (2 * AD_STAGE_F * 4)

__global__ __launch_bounds__(256) void adapter_down(
    const float* __restrict__ A, const float* __restrict__ W,
    const float* __restrict__ bias, float* __restrict__ C, int K)
{
    extern __shared__ float smem[];
    const int tid  = threadIdx.x;
    const int wid  = tid >> 5;
    const int lane = tid & 31;
    const int g    = lane >> 2;
    const int tig  = lane & 3;
    const int wm   = wid >> 1;
    const int wn   = wid & 1;
    const int m0   = blockIdx.x * 128;

    const int a_lrow = lane & 15;
    const int a_koff = (lane >> 4) * 4;
    const uint32_t sb = s2u(smem);

    auto load_stage = [&](int s, int b) {
        const uint32_t abase = sb + (uint32_t)(b * AD_STAGE_F) * 4;
        const uint32_t bbase = abase + 128 * A_LD * 4;
        const float* Ag = A + (size_t)m0 * K + s * 32;
        const float* Wg = W + (size_t)(s * 32) * A_DIM;
#pragma unroll
        for (int i = 0; i < 4; i++) {
            int c = tid + i * 256;
            int row = c >> 3, k4 = c & 7;
            cp16(abase + row * (A_LD * 4) + k4 * 16, Ag + (size_t)row * K + k4 * 4);
        }
#pragma unroll
        for (int i = 0; i < 2; i++) {
            int c = tid + i * 256;
            int kr = c >> 4, n4 = c & 15;
            cp16(bbase + kr * (AD_B_LD * 4) + n4 * 16, Wg + (size_t)kr * A_DIM + n4 * 4);
        }
        asm volatile("cp.async.commit_group;" ::: "memory");
    };

    float acc[2][4][4];
#pragma unroll
    for (int mi = 0; mi < 2; mi++)
#pragma unroll
        for (int ni = 0; ni < 4; ni++)
#pragma unroll
            for (int t = 0; t < 4; t++) acc[mi][ni][t] = 0.f;

    const int NS = K / 32;
    load_stage(0, 0);

    for (int s = 0; s < NS; s++) {
        const int buf = s & 1;
        if (s + 1 < NS) {
            load_stage(s + 1, buf ^ 1);
            asm volatile("cp.async.wait_group 1;" ::: "memory");
        } else {
            asm volatile("cp.async.wait_group 0;" ::: "memory");
        }
        __syncthreads();

        const uint32_t As_u = sb + (uint32_t)(buf * AD_STAGE_F) * 4;
        const float* Bs = smem + buf * AD_STAGE_F + 128 * A_LD;

#pragma unroll
        for (int ks = 0; ks < 4; ks++) {
            uint32_t afr[2][4];
#pragma unroll
            for (int mi = 0; mi < 2; mi++) {
                ldsm_x4(afr[mi], As_u +
                    (uint32_t)((wm * 32 + mi * 16 + a_lrow) * A_LD + ks * 8 + a_koff) * 4);
            }
            uint32_t bfr[4][2];
#pragma unroll
            for (int ni = 0; ni < 4; ni++) {
                const float* p = Bs + (ks * 8 + tig) * AD_B_LD + wn * 32 + ni * 8 + g;
                bfr[ni][0] = f2tf32(p[0]);
                bfr[ni][1] = f2tf32(p[4 * AD_B_LD]);
            }
#pragma unroll
            for (int mi = 0; mi < 2; mi++)
#pragma unroll
                for (int ni = 0; ni < 4; ni++)
                    mma_tf32(acc[mi][ni], afr[mi], bfr[ni]);
        }
        __syncthreads();
    }

#pragma unroll
    for (int mi = 0; mi < 2; mi++) {
        const int r0 = m0 + wm * 32 + mi * 16 + g;
#pragma unroll
        for (int ni = 0; ni < 4; ni++) {
            const int col = wn * 32 + ni * 8 + tig * 2;
            const float bx = bias[col], by = bias[col + 1];
#pragma unroll
            for (int hh = 0; hh < 2; hh++) {
                const int row = r0 + hh * 8;
                float cx = fmaxf(acc[mi][ni][hh * 2 + 0] + bx, 0.f);
                float cy = fmaxf(acc[mi][ni][hh * 2 + 1] + by, 0.f);
                *(float2*)(C + (size_t)row * A_DIM + col) = make_float2(cx, cy);
            }
        }
    }
}

// ---------------- LayerNorm kernels -------------------------------------------
__global__ __launch_bounds__(256) void ln_kernel(const float* __restrict__ x,
                                                 const float* __restrict__ g,
                                                 const float* __restrict__ b,
                                                 float* __restrict__ out) {
    const int warp = threadIdx.x >> 5, lane = threadIdx.x & 31;
    const int row = blockIdx.x * 8 + warp;
    const float4* xr = (const float4*)(x + (size_t)row * C_DIM);

    float4 v[8];
    float s = 0.f;
#pragma unroll
    for (int i = 0; i < 8; i++) {
        v[i] = xr[i * 32 + lane];
        s += v[i].x + v[i].y + v[i].z + v[i].w;
    }
#pragma unroll
    for (int off = 16; off > 0; off >>= 1)
        s += __shfl_xor_sync(0xFFFFFFFF, s, off);
    const float mean = s * (1.0f / 1024.0f);

    float sq = 0.f;
#pragma unroll
    for (int i = 0; i < 8; i++) {
        float dx = v[i].x - mean, dy = v[i].y - mean,
              dz = v[i].z - mean, dw = v[i].w - mean;
        sq += dx * dx + dy * dy + dz * dz + dw * dw;
    }
#pragma unroll
    for (int off = 16; off > 0; off >>= 1)
        sq += __shfl_xor_sync(0xFFFFFFFF, sq, off);
    const float inv = rsqrtf(sq * (1.0f / 1024.0f) + 1e-5f);

    float4* orow = (float4*)(out + (size_t)row * C_DIM);
    const float4* gv = (const float4*)g;
    const float4* bv = (const float4*)b;
#pragma unroll
    for (int i = 0; i < 8; i++) {
        const int c = i * 32 + lane;
        float4 gg = gv[c], bb = bv[c], o;
        o.x = (v[i].x - mean) * inv * gg.x + bb.x;
        o.y = (v[i].y - mean) * inv * gg.y + bb.y;
        o.z = (v[i].z - mean) * inv * gg.z + bb.z;
        o.w = (v[i].w - mean) * inv * gg.w + bb.w;
        orow[c] = o;
    }
}

__global__ __launch_bounds__(256) void ln_bf16_kernel(const float* __restrict__ x,
                                                      const float* __restrict__ g,
                                                      const float* __restrict__ b,
                                                      __nv_bfloat16* __restrict__ out) {
    const int warp = threadIdx.x >> 5, lane = threadIdx.x & 31;
    const int row = blockIdx.x * 8 + warp;
    const float4* xr = (const float4*)(x + (size_t)row * C_DIM);

    float4 v[8];
    float s = 0.f;
#pragma unroll
    for (int i = 0; i < 8; i++) {
        v[i] = xr[i * 32 + lane];
        s += v[i].x + v[i].y + v[i].z + v[i].w;
    }
#pragma unroll
    for (int off = 16; off > 0; off >>= 1)
        s += __shfl_xor_sync(0xFFFFFFFF, s, off);
    const float mean = s * (1.0f / 1024.0f);

    float sq = 0.f;
#pragma unroll
    for (int i = 0; i < 8; i++) {
        float dx = v[i].x - mean, dy = v[i].y - mean,
              dz = v[i].z - mean, dw = v[i].w - mean;
        sq += dx * dx + dy * dy + dz * dz + dw * dw;
    }
#pragma unroll
    for (int off = 16; off > 0; off >>= 1)
        sq += __shfl_xor_sync(0xFFFFFFFF, sq, off);
    const float inv = rsqrtf(sq * (1.0f / 1024.0f) + 1e-5f);

    __nv_bfloat162* orow = (__nv_bfloat162*)(out + (size_t)row * C_DIM);
    const float4* gv = (const float4*)g;
    const float4* bv = (const float4*)b;
#pragma unroll
    for (int i = 0; i < 8; i++) {
        const int c = i * 32 + lane;
        float4 gg = gv[c], bb = bv[c];
        float ox = (v[i].x - mean) * inv * gg.x + bb.x;
        float oy = (v[i].y - mean) * inv * gg.y + bb.y;
        float oz = (v[i].z - mean) * inv * gg.z + bb.z;
        float ow = (v[i].w - mean) * inv * gg.w + bb.w;
        orow[c * 2]     = __floats2bfloat162_rn(ox, oy);
        orow[c * 2 + 1] = __floats2bfloat162_rn(oz, ow);
    }
}

// ================= Flash attention (unchanged R9) =============================
#define ATT_LD 68
#define ATT_QT 128
#define ATT_SMEM ((ATT_QT + 64 + 64 + ATT_QT) * ATT_LD * 4)

__global__ __launch_bounds__(128) void attn_mma(const float* __restrict__ q,
                                                const float* __restrict__ k,
                                                const float* __restrict__ v,
                                                float* __restrict__ y) {
    extern __shared__ float sm[];
    float* Qs = sm;
    float* Ks = Qs + ATT_QT * ATT_LD;
    float* Vt = Ks + 64 * ATT_LD;

    const int bh = blockIdx.x;
    const int b = bh >> 4, h = bh & 15;
    const int qb = (gridDim.y - 1) - blockIdx.y;
    const int q0 = qb * ATT_QT;
    const int tid = threadIdx.x;
    const int w = tid >> 5, lane = tid & 31;
    const int g = lane >> 2, tig = lane & 3;

    const int a_lrow = lane & 15;
    const int a_koff = (lane >> 4) * 4;
    const int b_tile = lane >> 4;
    const int b_lrow = lane & 7;
    const int b_koff = ((lane >> 3) & 1) * 4;

    const uint32_t sb   = s2u(sm);
    const uint32_t Qs_u = sb;
    const uint32_t Ks_u = sb + (uint32_t)(ATT_QT * ATT_LD) * 4;
    const uint32_t Vt_u = Ks_u + (uint32_t)(64 * ATT_LD) * 4;
    const uint32_t Ps_u = Vt_u + (uint32_t)(64 * ATT_LD) * 4;
    float* Ps = Vt + 64 * ATT_LD;

    const float* qp = q + (size_t)b * T_LEN * C_DIM + h * HDIM;
    const float* kp = k + (size_t)b * T_LEN * C_DIM + h * HDIM;
    const float* vp = v + (size_t)b * T_LEN * C_DIM + h * HDIM;

    {
        const float* src = qp + (size_t)(q0 + tid) * C_DIM;
        float* dst = Qs + tid * ATT_LD;
#pragma unroll
        for (int i = 0; i < 16; i++) {
            float4 t = *(const float4*)(src + i * 4);
            t.x *= 0.125f; t.y *= 0.125f; t.z *= 0.125f; t.w *= 0.125f;
            *(float4*)(dst + i * 4) = t;
        }
    }

    float of[2][8][4];
#pragma unroll
    for (int mi = 0; mi < 2; mi++)
#pragma unroll
        for (int dc = 0; dc < 8; dc++)
#pragma unroll
            for (int t = 0; t < 4; t++) of[mi][dc][t] = 0.f;
    float mrow[2][2] = {{-1e30f, -1e30f}, {-1e30f, -1e30f}};
    float lrow[2][2] = {{0.f, 0.f}, {0.f, 0.f}};

    const int kb_max = 2 * qb + 1;
    const int wmaxrow = q0 + w * 32 + 31;

    for (int kb = 0; kb <= kb_max; kb++) {
        __syncthreads();
        {
            const int r = tid >> 1, s0 = (tid & 1) * 32;
            const float* ks = kp + (size_t)(kb * 64 + r) * C_DIM + s0;
            float* kd = Ks + r * ATT_LD + s0;
#pragma unroll
            for (int i = 0; i < 8; i++)
                *(float4*)(kd + i * 4) = *(const float4*)(ks + i * 4);
            const float* vs = vp + (size_t)(kb * 64 + r) * C_DIM + s0;
#pragma unroll
            for (int i = 0; i < 8; i++) {
                float4 t = *(const float4*)(vs + i * 4);
                const int d = s0 + i * 4;
                Vt[(d + 0) * ATT_LD + r] = t.x;
                Vt[(d + 1) * ATT_LD + r] = t.y;
                Vt[(d + 2) * ATT_LD + r] = t.z;
                Vt[(d + 3) * ATT_LD + r] = t.w;
            }
        }
        __syncthreads();

        if (kb * 64 > wmaxrow) continue;

        float sf[2][8][4];
#pragma unroll
        for (int mi = 0; mi < 2; mi++)
#pragma unroll
            for (int nc = 0; nc < 8; nc++)
#pragma unroll
                for (int t = 0; t < 4; t++) sf[mi][nc][t] = 0.f;
#pragma unroll
        for (int kc = 0; kc < 8; kc++) {
            uint32_t af[2][4];
            ldsm_x4(af[0], Qs_u +
                (uint32_t)((w * 32 + a_lrow) * ATT_LD + kc * 8 + a_koff) * 4);
            ldsm_x4(af[1], Qs_u +
                (uint32_t)((w * 32 + 16 + a_lrow) * ATT_LD + kc * 8 + a_koff) * 4);
#pragma unroll
            for (int nc = 0; nc < 8; nc += 2) {
                uint32_t bf[4];
                ldsm_x4(bf, Ks_u +
                    (uint32_t)(((nc + b_tile) * 8 + b_lrow) * ATT_LD + kc * 8 + b_koff) * 4);
                mma_tf32(sf[0][nc],     af[0], bf);
                mma_tf32(sf[1][nc],     af[1], bf);
                mma_tf32(sf[0][nc + 1], af[0], bf + 2);
                mma_tf32(sf[1][nc + 1], af[1], bf + 2);
            }
        }

#pragma unroll
        for (int mi = 0; mi < 2; mi++) {
            const int base = q0 + w * 32 + mi * 16;
            if (kb * 64 + 63 > base) {
                const int r0 = base + g, r1 = base + g + 8;
#pragma unroll
                for (int nc = 0; nc < 8; nc++) {
                    const int j0 = kb * 64 + nc * 8 + 2 * tig;
                    if (j0 > r0)     sf[mi][nc][0] = -1e30f;
                    if (j0 + 1 > r0) sf[mi][nc][1] = -1e30f;
                    if (j0 > r1)     sf[mi][nc][2] = -1e30f;
                    if (j0 + 1 > r1) sf[mi][nc][3] = -1e30f;
                }
            }
            float ml0 = -1e30f, ml1 = -1e30f;
#pragma unroll
            for (int nc = 0; nc < 8; nc++) {
                ml0 = fmaxf(ml0, fmaxf(sf[mi][nc][0], sf[mi][nc][1]));
                ml1 = fmaxf(ml1, fmaxf(sf[mi][nc][2], sf[mi][nc][3]));
            }
            ml0 = fmaxf(ml0, __shfl_xor_sync(0xFFFFFFFF, ml0, 1));
            ml0 = fmaxf(ml0, __shfl_xor_sync(0xFFFFFFFF, ml0, 2));
            ml1 = fmaxf(ml1, __shfl_xor_sync(0xFFFFFFFF, ml1, 1));
            ml1 = fmaxf(ml1, __shfl_xor_sync(0xFFFFFFFF, ml1, 2));

            const float mn0 = fmaxf(mrow[mi][0], ml0);
            const float mn1 = fmaxf(mrow[mi][1], ml1);
            const float al0 = __expf(mrow[mi][0] - mn0);
            const float al1 = __expf(mrow[mi][1] - mn1);
            lrow[mi][0] *= al0; lrow[mi][1] *= al1;
#pragma unroll
            for (int dc = 0; dc < 8; dc++) {
                of[mi][dc][0] *= al0; of[mi][dc][1] *= al0;
                of[mi][dc][2] *= al1; of[mi][dc][3] *= al1;
            }
#pragma unroll
            for (int nc = 0; nc < 8; nc++) {
                sf[mi][nc][0] = __expf(sf[mi][nc][0] - mn0);
                sf[mi][nc][1] = __expf(sf[mi][nc][1] - mn0);
                sf[mi][nc][2] = __expf(sf[mi][nc][2] - mn1);
                sf[mi][nc][3] = __expf(sf[mi][nc][3] - mn1);
                lrow[mi][0] += sf[mi][nc][0] + sf[mi][nc][1];
                lrow[mi][1] += sf[mi][nc][2] + sf[mi][nc][3];
            }
            mrow[mi][0] = mn0; mrow[mi][1] = mn1;

            float* pw = Ps + (w * 32 + mi * 16) * ATT_LD;
#pragma unroll
            for (int nc = 0; nc < 8; nc++) {
                pw[g * ATT_LD + nc * 8 + 2 * tig]           = sf[mi][nc][0];
                pw[g * ATT_LD + nc * 8 + 2 * tig + 1]       = sf[mi][nc][1];
                pw[(g + 8) * ATT_LD + nc * 8 + 2 * tig]     = sf[mi][nc][2];
                pw[(g + 8) * ATT_LD + nc * 8 + 2 * tig + 1] = sf[mi][nc][3];
            }
        }
        __syncwarp();

#pragma unroll
        for (int kc = 0; kc < 8; kc++) {
            uint32_t pf[2][4];
            ldsm_x4(pf[0], Ps_u +
                (uint32_t)((w * 32 + a_lrow) * ATT_LD + kc * 8 + a_koff) * 4);
            ldsm_x4(pf[1], Ps_u +
                (uint32_t)((w * 32 + 16 + a_lrow) * ATT_LD + kc * 8 + a_koff) * 4);
#pragma unroll
            for (int dc = 0; dc < 8; dc += 2) {
                uint32_t bf[4];
                ldsm_x4(bf, Vt_u +
                    (uint32_t)(((dc + b_tile) * 8 + b_lrow) * ATT_LD + kc * 8 + b_koff) * 4);
                mma_tf32(of[0][dc],     pf[0], bf);
                mma_tf32(of[1][dc],     pf[1], bf);
                mma_tf32(of[0][dc + 1], pf[0], bf + 2);
                mma_tf32(of[1][dc + 1], pf[1], bf + 2);
            }
        }
        __syncwarp();
    }

#pragma unroll
    for (int mi = 0; mi < 2; mi++) {
        float l0 = lrow[mi][0], l1 = lrow[mi][1];
        l0 += __shfl_xor_sync(0xFFFFFFFF, l0, 1);
        l0 += __shfl_xor_sync(0xFFFFFFFF, l0, 2);
        l1 += __shfl_xor_sync(0xFFFFFFFF, l1, 1);
        l1 += __shfl_xor_sync(0xFFFFFFFF, l1, 2);
        const float inv0 = 1.f / l0, inv1 = 1.f / l1;

        float* yp = y + ((size_t)b * T_LEN + q0 + w * 32 + mi * 16) * C_DIM + h * HDIM;
#pragma unroll
        for (int dc = 0; dc < 8; dc++) {
            const int col = dc * 8 + 2 * tig;
            *(float2*)(yp + (size_t)g * C_DIM + col) =
                make_float2(of[mi][dc][0] * inv0, of[mi][dc][1] * inv0);
            *(float2*)(yp + (size_t)(g + 8) * C_DIM + col) =
                make_float2(of[mi][dc][2] * inv1, of[mi][dc][3] * inv1);
        }
    }
}

// -----------------------------------------------------------------------------
extern "C" void kernel_launch(void* const* d_in, const int* in_sizes, int n_in,
                              void* d_out, int out_size) {
    const float* x     = (const float*)d_in[0];
    const float* ln1_g = (const float*)d_in[1];
    const float* ln1_b = (const float*)d_in[2];
    const float* ln2_g = (const float*)d_in[3];
    const float* ln2_b = (const float*)d_in[4];
    const float* ln3_g = (const float*)d_in[5];
    const float* ln3_b = (const float*)d_in[6];
    const float* wq = (const float*)d_in[7];   const float* bq = (const float*)d_in[8];
    const float* wk = (const float*)d_in[9];   const float* bk = (const float*)d_in[10];
    const float* wv = (const float*)d_in[11];  const float* bv = (const float*)d_in[12];
    const float* wo = (const float*)d_in[13];  const float* bo = (const float*)d_in[14];
    const float* w1 = (const float*)d_in[15];  const float* b1 = (const float*)d_in[16];
    const float* w2 = (const float*)d_in[17];  const float* b2 = (const float*)d_in[18];
    const float* wd = (const float*)d_in[19];  const float* bd = (const float*)d_in[20];
    const float* wu = (const float*)d_in[21];  const float* bu = (const float*)d_in[22];
    float* out = (float*)d_out;

    float *h, *q, *k, *v, *y, *hidden, *mlp, *n3, *ad1;
    float *wqt, *wkt, *wvt, *wot;
    __nv_bfloat16 *mb, *ffb, *w1b, *w2b;
    cudaGetSymbolAddress((void**)&h,      g_h);
    cudaGetSymbolAddress((void**)&q,      g_q);
    cudaGetSymbolAddress((void**)&k,      g_k);
    cudaGetSymbolAddress((void**)&v,      g_v);
    cudaGetSymbolAddress((void**)&y,      g_y);
    cudaGetSymbolAddress((void**)&hidden, g_hidden);
    cudaGetSymbolAddress((void**)&mlp,    g_mlp);
    cudaGetSymbolAddress((void**)&n3,     g_n3);
    cudaGetSymbolAddress((void**)&ad1,    g_ad1);
    cudaGetSymbolAddress((void**)&wqt,    g_wqt);
    cudaGetSymbolAddress((void**)&wkt,    g_wkt);
    cudaGetSymbolAddress((void**)&wvt,    g_wvt);
    cudaGetSymbolAddress((void**)&wot,    g_wot);
    cudaGetSymbolAddress((void**)&mb,     g_mb);
    cudaGetSymbolAddress((void**)&ffb,    g_ffb);
    cudaGetSymbolAddress((void**)&w1b,    g_w1b);
    cudaGetSymbolAddress((void**)&w2b,    g_w2b);

    cudaFuncSetAttribute(qkv_gemm, cudaFuncAttributeMaxDynamicSharedMemorySize, tn_smem<4>());
    cudaFuncSetAttribute(tn_gemm<0, 1, 2>, cudaFuncAttributeMaxDynamicSharedMemorySize, tn_smem<2>());
    cudaFuncSetAttribute(tc_gemm<0, 2, 2>, cudaFuncAttributeMaxDynamicSharedMemorySize, gemm_smem<2>());
    cudaFuncSetAttribute(adapter_down, cudaFuncAttributeMaxDynamicSharedMemorySize, AD_SMEM);
    cudaFuncSetAttribute(attn_mma, cudaFuncAttributeMaxDynamicSharedMemorySize, ATT_SMEM);
    cudaFuncSetAttribute(bf16_gemm<1, true>,  cudaFuncAttributeMaxDynamicSharedMemorySize, BH_SMEM);
    cudaFuncSetAttribute(bf16_gemm<0, false>, cudaFuncAttributeMaxDynamicSharedMemorySize, BH_SMEM);

    // Weight conversions/transposes (independent; run first)
    wt_bf16_kernel<<<dim3(FF_DIM / 32, C_DIM / 32), dim3(32, 8)>>>(w1, w1b, C_DIM, FF_DIM);
    wt_bf16_kernel<<<dim3(C_DIM / 32, FF_DIM / 32), dim3(32, 8)>>>(w2, w2b, FF_DIM, C_DIM);
    wt_f32_kernel<<<dim3(C_DIM / 32, C_DIM / 32), dim3(32, 8)>>>(wq, wqt, C_DIM, C_DIM);
    wt_f32_kernel<<<dim3(C_DIM / 32, C_DIM / 32), dim3(32, 8)>>>(wk, wkt, C_DIM, C_DIM);
    wt_f32_kernel<<<dim3(C_DIM / 32, C_DIM / 32), dim3(32, 8)>>>(wv, wvt, C_DIM, C_DIM);
    wt_f32_kernel<<<dim3(C_DIM / 32, C_DIM / 32), dim3(32, 8)>>>(wo, wot, C_DIM, C_DIM);

    // LN1(x), LN3(x)
    ln_kernel<<<M_ROWS / 8, 256>>>(x, ln1_g, ln1_b, h);
    ln_kernel<<<M_ROWS / 8, 256>>>(x, ln3_g, ln3_b, n3);

    // fused QKV projection (tf32, transposed-B all-ldmatrix)
    qkv_gemm<<<dim3(24, 32), 256, tn_smem<4>()>>>(h, wqt, wkt, wvt, bq, bk, bv, q, k, v);

    // Causal attention
    attn_mma<<<dim3(4 * NHEAD, T_LEN / ATT_QT), 128, ATT_SMEM>>>(q, k, v, y);

    // Output projection + residual -> hidden (tf32 transposed-B)
    tn_gemm<0, 1, 2><<<dim3(8, 64), 256, tn_smem<2>()>>>(y, wot, bo, x, nullptr, hidden, C_DIM, C_DIM);

    // adapter-down on ln3(x)
    adapter_down<<<32, 256, AD_SMEM>>>(n3, wd, bd, ad1, C_DIM);

    // MLP on ln2(hidden) — bf16 tensor cores
    ln_bf16_kernel<<<M_ROWS / 8, 256>>>(hidden, ln2_g, ln2_b, mb);
    bf16_gemm<1, true><<<dim3(FF_DIM / 128, M_ROWS / 128), 256, BH_SMEM>>>(
        mb, w1b, b1, ffb, FF_DIM, C_DIM);
    bf16_gemm<0, false><<<dim3(C_DIM / 128, M_ROWS / 128), 256, BH_SMEM>>>(
        ffb, w2b, b2, mlp, C_DIM, FF_DIM);

    // adapter-up + final combine: out = (ad1@wu + bu) + 2*hidden + mlp
    tc_gemm<0, 2, 2><<<dim3(8, 64), 256, gemm_smem<2>()>>>(ad1, wu, bu, hidden, mlp, out, C_DIM, A_DIM);
}